// round 2
// baseline (speedup 1.0000x reference)
#include <cuda_runtime.h>

// VQ nearest-neighbor: z_e [B=32, C=64, H=64, W=64] f32, embedding [K=1024, C=64] f32
// out[b,c,h,w] = embedding[argmin_k(||e_k||^2 - 2 z.e_k), c]
// N = B*H*W = 131072 positions.

#define C_DIM   64
#define K_DIM   1024
#define HW      4096        // H*W
#define KTILE   128
#define NTHREADS 256

__global__ __launch_bounds__(NTHREADS, 2)
void vq_argmin_kernel(const float* __restrict__ z_e,
                      const float* __restrict__ emb,
                      float* __restrict__ out)
{
    __shared__ float sE[KTILE * C_DIM];   // 32 KB
    __shared__ float sN[KTILE];           // code norms

    const int p  = blockIdx.x * NTHREADS + threadIdx.x;   // position index in [0, N)
    const int b  = p >> 12;               // p / HW
    const int hw = p & (HW - 1);          // p % HW

    // Load this thread's 64-dim z vector into registers.
    // Stride HW between channels -> constant immediate offsets, coalesced across threads.
    const float* zp = z_e + (size_t)b * C_DIM * HW + hw;
    float z[C_DIM];
#pragma unroll
    for (int c = 0; c < C_DIM; c++) z[c] = zp[(size_t)c * HW];

    float best  = 3.402823466e+38f;
    int   bestk = 0;

    for (int t = 0; t < K_DIM; t += KTILE) {
        __syncthreads();
        // Cooperative tile load: KTILE*C floats = 2048 float4, 8 per thread.
        {
            const float4* src = (const float4*)(emb + (size_t)t * C_DIM);
            float4*       dst = (float4*)sE;
#pragma unroll
            for (int i = 0; i < (KTILE * C_DIM / 4) / NTHREADS; i++)
                dst[threadIdx.x + i * NTHREADS] = src[threadIdx.x + i * NTHREADS];
        }
        __syncthreads();
        // Per-tile code norms (threads 0..KTILE-1).
        if (threadIdx.x < KTILE) {
            const float* e = &sE[threadIdx.x * C_DIM];
            float s0 = 0.f, s1 = 0.f, s2 = 0.f, s3 = 0.f;
#pragma unroll
            for (int c = 0; c < C_DIM; c += 4) {
                s0 += e[c + 0] * e[c + 0];
                s1 += e[c + 1] * e[c + 1];
                s2 += e[c + 2] * e[c + 2];
                s3 += e[c + 3] * e[c + 3];
            }
            sN[threadIdx.x] = (s0 + s1) + (s2 + s3);
        }
        __syncthreads();

        // Main loop: for each code in the tile, fp32 dot with 4-way accumulator ILP.
#pragma unroll 2
        for (int k = 0; k < KTILE; k++) {
            const float* e = &sE[k * C_DIM];   // warp-uniform -> smem broadcast
            float d0 = 0.f, d1 = 0.f, d2 = 0.f, d3 = 0.f;
#pragma unroll
            for (int c = 0; c < C_DIM; c += 4) {
                d0 += z[c + 0] * e[c + 0];
                d1 += z[c + 1] * e[c + 1];
                d2 += z[c + 2] * e[c + 2];
                d3 += z[c + 3] * e[c + 3];
            }
            float dist = sN[k] - 2.f * ((d0 + d1) + (d2 + d3));
            if (dist < best) { best = dist; bestk = t + k; }  // strict < : first index wins (matches argmin)
        }
    }

    // Gather winning code and scatter to [B, C, H, W] layout (coalesced across threads).
    const float* e = emb + (size_t)bestk * C_DIM;
    float* op = out + (size_t)b * C_DIM * HW + hw;
#pragma unroll
    for (int c = 0; c < C_DIM; c++) op[(size_t)c * HW] = e[c];
}

extern "C" void kernel_launch(void* const* d_in, const int* in_sizes, int n_in,
                              void* d_out, int out_size)
{
    const float* z_e = (const float*)d_in[0];   // [32, 64, 64, 64]
    const float* emb = (const float*)d_in[1];   // [1024, 64]
    float*       out = (float*)d_out;           // [32, 64, 64, 64]

    const int N = in_sizes[0] / C_DIM;          // 131072
    vq_argmin_kernel<<<N / NTHREADS, NTHREADS>>>(z_e, emb, out);
}

// round 3
// speedup vs baseline: 1.6513x; 1.6513x over previous
#include <cuda_runtime.h>

// VQ nearest-neighbor, GEMM-tiled with packed f32x2 FMA.
// z_e [B=32, C=64, H=64, W=64] f32, embedding [K=1024, C=64] f32
// dist(p,k) = ||e_k||^2 - 2 z_p . e_k  ->  norm[k] + (-2 z_p) . e_k
// Block: MTILE=128 positions x all K=1024 codes (KTILE=64 per iteration).
// Thread (256/block): 8 positions x 4 codes, accumulated as f32x2 position-pairs.

#define C_DIM    64
#define K_DIM    1024
#define HW       4096
#define MTILE    128
#define KTILE    64
#define NTHREADS 256

typedef unsigned long long u64;

__device__ float g_norms[K_DIM];

__device__ __forceinline__ u64 pack2(float x) {
    u64 r; asm("mov.b64 %0, {%1, %1};" : "=l"(r) : "f"(x)); return r;
}
__device__ __forceinline__ void fma2(u64 &d, u64 a, u64 b) {
    asm("fma.rn.f32x2 %0, %1, %2, %0;" : "+l"(d) : "l"(a), "l"(b));
}
__device__ __forceinline__ void unpack2(u64 v, float &lo, float &hi) {
    asm("mov.b64 {%0, %1}, %2;" : "=f"(lo), "=f"(hi) : "l"(v));
}

union F4U2 { float4 f4; u64 u2[2]; };

// ---- Kernel 1: codebook norms ||e_k||^2 -> g_norms ----
__global__ void vq_norms_kernel(const float* __restrict__ emb) {
    int k = blockIdx.x * blockDim.x + threadIdx.x;
    const float4* e = (const float4*)(emb + (size_t)k * C_DIM);
    float s = 0.f;
#pragma unroll
    for (int i = 0; i < C_DIM / 4; i++) {
        float4 v = e[i];
        s += v.x * v.x + v.y * v.y + v.z * v.z + v.w * v.w;
    }
    g_norms[k] = s;
}

// ---- Kernel 2: fused distance-GEMM + argmin + gather ----
__global__ __launch_bounds__(NTHREADS, 2)
void vq_main_kernel(const float* __restrict__ z_e,
                    const float* __restrict__ emb,
                    float* __restrict__ out)
{
    __shared__ float  zs[C_DIM][MTILE];    // 32 KB, holds -2*z, layout [c][m]
    __shared__ float4 esv[C_DIM][KTILE/4]; // 16 KB, E tile [c][k4] with XOR swizzle on k4

    const int tid  = threadIdx.x;
    const int col  = tid & 15;     // code group: codes col*4 .. col*4+3 within tile
    const int rowg = tid >> 4;     // position group: positions rowg*8 .. rowg*8+7
    const int p0   = blockIdx.x * MTILE;
    const int b    = p0 >> 12;
    const int hw0  = p0 & (HW - 1);

    // ---- Load Z tile: zs[c][m] = -2 * z_e[b, c, hw0+m] (fully coalesced) ----
    {
        const float4* src = (const float4*)(z_e + (size_t)b * C_DIM * HW + hw0);
#pragma unroll
        for (int i = 0; i < (MTILE * C_DIM / 4) / NTHREADS; i++) {
            int idx = tid + i * NTHREADS;      // 0..2047
            int c = idx >> 5, m4 = idx & 31;
            float4 v = src[(size_t)c * (HW / 4) + m4];
            v.x *= -2.f; v.y *= -2.f; v.z *= -2.f; v.w *= -2.f;
            *(float4*)&zs[c][m4 * 4] = v;
        }
    }

    float best[8]; int bestk[8];
#pragma unroll
    for (int j = 0; j < 8; j++) { best[j] = 3.402823466e+38f; bestk[j] = 0; }

    for (int t = 0; t < K_DIM; t += KTILE) {
        __syncthreads();
        // ---- Load+transpose E tile into swizzled [c][k4] layout ----
        // idx -> k = idx & 63, c4 = idx >> 6: conflict-free STS (banks fully spread).
        {
            const float4* esrc = (const float4*)(emb + (size_t)t * C_DIM);
#pragma unroll
            for (int i = 0; i < (KTILE * C_DIM / 4) / NTHREADS; i++) {
                int idx = tid + i * NTHREADS;  // 0..1023
                int k = idx & 63, c4 = idx >> 6;
                float4 v = esrc[(size_t)k * (C_DIM / 4) + c4];
                int k4 = k >> 2, r = k & 3;
                float* d0 = &((float*)&esv[c4 * 4 + 0][k4 ^ ((c4 * 4 + 0) & 15)])[r];
                float* d1 = &((float*)&esv[c4 * 4 + 1][k4 ^ ((c4 * 4 + 1) & 15)])[r];
                float* d2 = &((float*)&esv[c4 * 4 + 2][k4 ^ ((c4 * 4 + 2) & 15)])[r];
                float* d3 = &((float*)&esv[c4 * 4 + 3][k4 ^ ((c4 * 4 + 3) & 15)])[r];
                *d0 = v.x; *d1 = v.y; *d2 = v.z; *d3 = v.w;
            }
        }
        __syncthreads();

        // ---- Register-blocked distance accumulation (f32x2) ----
        u64 acc[4][4];
#pragma unroll
        for (int pp = 0; pp < 4; pp++)
#pragma unroll
            for (int k = 0; k < 4; k++) acc[pp][k] = 0ull;

#pragma unroll 4
        for (int c = 0; c < C_DIM; c++) {
            float4 ef = esv[c][col ^ (c & 15)];         // this thread's 4 codes at dim c
            u64 e0 = pack2(ef.x), e1 = pack2(ef.y), e2 = pack2(ef.z), e3 = pack2(ef.w);
            F4U2 za, zb;
            za.f4 = *(const float4*)&zs[c][rowg * 8];
            zb.f4 = *(const float4*)&zs[c][rowg * 8 + 4];
            u64 zp0 = za.u2[0], zp1 = za.u2[1], zp2 = zb.u2[0], zp3 = zb.u2[1];
            fma2(acc[0][0], zp0, e0); fma2(acc[0][1], zp0, e1);
            fma2(acc[0][2], zp0, e2); fma2(acc[0][3], zp0, e3);
            fma2(acc[1][0], zp1, e0); fma2(acc[1][1], zp1, e1);
            fma2(acc[1][2], zp1, e2); fma2(acc[1][3], zp1, e3);
            fma2(acc[2][0], zp2, e0); fma2(acc[2][1], zp2, e1);
            fma2(acc[2][2], zp2, e2); fma2(acc[2][3], zp2, e3);
            fma2(acc[3][0], zp3, e0); fma2(acc[3][1], zp3, e1);
            fma2(acc[3][2], zp3, e2); fma2(acc[3][3], zp3, e3);
        }

        // ---- Per-tile epilogue: dist = norm[k] + acc; keep running argmin ----
        float nk[4];
#pragma unroll
        for (int k = 0; k < 4; k++) nk[k] = g_norms[t + col * 4 + k];
#pragma unroll
        for (int pp = 0; pp < 4; pp++) {
#pragma unroll
            for (int k = 0; k < 4; k++) {
                float lo, hi; unpack2(acc[pp][k], lo, hi);
                float d0 = nk[k] + lo;
                float d1 = nk[k] + hi;
                int kk = t + col * 4 + k;
                int j0 = 2 * pp, j1 = 2 * pp + 1;
                if (d0 < best[j0]) { best[j0] = d0; bestk[j0] = kk; }
                if (d1 < best[j1]) { best[j1] = d1; bestk[j1] = kk; }
            }
        }
    }

    // ---- Cross-lane argmin reduce over the 16 code groups (cols share a 16-lane group) ----
#pragma unroll
    for (int off = 8; off >= 1; off >>= 1) {
#pragma unroll
        for (int j = 0; j < 8; j++) {
            float ob = __shfl_xor_sync(0xFFFFFFFFu, best[j], off);
            int   ok = __shfl_xor_sync(0xFFFFFFFFu, bestk[j], off);
            if (ob < best[j] || (ob == best[j] && ok < bestk[j])) {
                best[j] = ob; bestk[j] = ok;
            }
        }
    }

    // ---- Publish winners (alias dead zs region), then cooperative gather-scatter ----
    __syncthreads();                       // everyone done reading zs/esv
    int* sIdx = (int*)&zs[0][0];
    if (col == 0) {
#pragma unroll
        for (int j = 0; j < 8; j++) sIdx[rowg * 8 + j] = bestk[j];
    }
    __syncthreads();

    const int m  = tid & 127;
    const int ch = (tid >> 7) * 32;        // this thread writes channels ch..ch+31 of position m
    const int kidx = sIdx[m];
    const float4* ev = (const float4*)(emb + (size_t)kidx * C_DIM);
    float* op = out + (size_t)b * C_DIM * HW + hw0 + m;
#pragma unroll
    for (int c4 = 0; c4 < 8; c4++) {
        float4 v = ev[(ch >> 2) + c4];
        op[(size_t)(ch + c4 * 4 + 0) * HW] = v.x;
        op[(size_t)(ch + c4 * 4 + 1) * HW] = v.y;
        op[(size_t)(ch + c4 * 4 + 2) * HW] = v.z;
        op[(size_t)(ch + c4 * 4 + 3) * HW] = v.w;
    }
}

extern "C" void kernel_launch(void* const* d_in, const int* in_sizes, int n_in,
                              void* d_out, int out_size)
{
    const float* z_e = (const float*)d_in[0];   // [32, 64, 64, 64]
    const float* emb = (const float*)d_in[1];   // [1024, 64]
    float*       out = (float*)d_out;

    vq_norms_kernel<<<K_DIM / 256, 256>>>(emb);
    const int N = in_sizes[0] / C_DIM;          // 131072
    vq_main_kernel<<<N / MTILE, NTHREADS>>>(z_e, emb, out);
}

// round 5
// speedup vs baseline: 2.1736x; 1.3163x over previous
#include <cuda_runtime.h>
#include <cstdint>

#define C_DIM  64
#define K_DIM  1024
#define HW     4096
#define NPOS   131072
#define BTILE  128                 // codes per smem tile
#define NBT    (K_DIM / BTILE)     // 8

// ---------- static device scratch ----------
__device__ float g_zh[(size_t)NPOS * C_DIM];   // tf32 hi of -2*z, permuted rows
__device__ float g_zl[(size_t)NPOS * C_DIM];   // tf32 lo
__device__ float g_eh[K_DIM * C_DIM];          // tf32 hi of e, permuted rows
__device__ float g_el[K_DIM * C_DIM];          // tf32 lo
__device__ float g_nrm[K_DIM];                 // ||e_k||^2 (fp32 exact)

__device__ __forceinline__ float tf32_rna(float v) {
    uint32_t u; asm("cvt.rna.tf32.f32 %0, %1;" : "=r"(u) : "f"(v));
    return __uint_as_float(u);
}

// Fragment-order permutation of a 64-float row, swizzled by row low bits.
// dim c -> (ks=c>>3, c0=c&3, j=(c>>2)&1); 8B unit u = ks*4+c0, swizzle by row bits 0..2.
__device__ __forceinline__ int permq(int c, int r) {
    int u = ((c >> 3) * 4 + (c & 3)) ^ (((r & 3) << 2) | ((r >> 2) & 1));
    return u * 2 + ((c >> 2) & 1);
}

// ---------- prep kernels ----------
__global__ void prep_nrm(const float* __restrict__ emb) {
    int k = blockIdx.x * blockDim.x + threadIdx.x;
    const float4* e = (const float4*)(emb + (size_t)k * C_DIM);
    float s = 0.f;
#pragma unroll
    for (int i = 0; i < C_DIM / 4; i++) {
        float4 v = e[i];
        s += v.x * v.x + v.y * v.y + v.z * v.z + v.w * v.w;
    }
    g_nrm[k] = s;
}

__global__ void prep_e(const float* __restrict__ emb) {
    int i = blockIdx.x * 256 + threadIdx.x;        // 65536 elements
    int k = i >> 6, c = i & 63;
    float v  = emb[i];
    float hi = tf32_rna(v);
    float lo = tf32_rna(v - hi);
    int o = k * C_DIM + permq(c, k & 7);
    g_eh[o] = hi;
    g_el[o] = lo;
}

// [b][c][hw] -> permuted tf32 split of (-2z), row-major [p][64]
__global__ void prep_z(const float* __restrict__ z) {
    __shared__ float s[64][65];
    int b  = blockIdx.x >> 6;
    int x0 = (blockIdx.x & 63) * 64;
    const float* src = z + (size_t)b * C_DIM * HW + x0;
    int t = threadIdx.x;
#pragma unroll
    for (int i = 0; i < 16; i++) {
        int idx = t + i * 256;
        int c = idx >> 6, x = idx & 63;
        s[c][x] = -2.f * src[(size_t)c * HW + x];
    }
    __syncthreads();
    size_t prow = (size_t)b * HW + x0;
#pragma unroll
    for (int i = 0; i < 16; i++) {
        int idx = t + i * 256;
        int pl = idx >> 6, c = idx & 63;
        float v  = s[c][pl];
        float hi = tf32_rna(v);
        float lo = tf32_rna(v - hi);
        size_t o = (prow + pl) * C_DIM + permq(c, pl & 7);
        g_zh[o] = hi;
        g_zl[o] = lo;
    }
}

// ---------- mma + cp.async helpers ----------
__device__ __forceinline__ void mma8(float* d, const uint32_t* a, uint2 b) {
    asm volatile("mma.sync.aligned.m16n8k8.row.col.f32.tf32.tf32.f32 "
        "{%0,%1,%2,%3}, {%4,%5,%6,%7}, {%8,%9}, {%0,%1,%2,%3};"
        : "+f"(d[0]), "+f"(d[1]), "+f"(d[2]), "+f"(d[3])
        : "r"(a[0]), "r"(a[1]), "r"(a[2]), "r"(a[3]), "r"(b.x), "r"(b.y));
}
__device__ __forceinline__ void cp16(void* dst_smem, const void* src) {
    uint32_t d;
    asm("{ .reg .u64 t; cvta.to.shared.u64 t, %1; cvt.u32.u64 %0, t; }" : "=r"(d) : "l"(dst_smem));
    asm volatile("cp.async.cg.shared.global [%0], [%1], 16;" :: "r"(d), "l"(src) : "memory");
}
#define CP_COMMIT() asm volatile("cp.async.commit_group;" ::: "memory")
#define CP_WAIT1()  asm volatile("cp.async.wait_group 1;" ::: "memory")
#define CP_WAIT0()  asm volatile("cp.async.wait_group 0;" ::: "memory")

// smem: B double buffer [2][128 codes][hi 256B | lo at +32KB], norms, idx
#define SM_NRM  131072
#define SM_IDX  135168
#define SM_TOT  135680

__device__ __forceinline__ void copy_tile(int t, char* dst, int tid) {
#pragma unroll
    for (int i = 0; i < 16; i++) {
        int u = tid + i * 256;                     // 0..4095 16B units
        const float* src = (i < 8)
            ? (g_eh + (size_t)(t * BTILE + (u >> 4)) * C_DIM + (u & 15) * 4)
            : (g_el + (size_t)(t * BTILE + ((u - 2048) >> 4)) * C_DIM + (u & 15) * 4);
        cp16(dst + (size_t)u * 16, src);
    }
}

// ---------- main kernel ----------
__global__ __launch_bounds__(256, 1)
void vq_mma(const float* __restrict__ emb, float* __restrict__ out)
{
    extern __shared__ char smem[];
    float* nsm  = (float*)(smem + SM_NRM);
    int*   sIdx = (int*)(smem + SM_IDX);

    const int tid  = threadIdx.x;
    const int lane = tid & 31, warp = tid >> 5;
    const int c0   = lane & 3, r = lane >> 2;      // r: 0..7
    const int p0   = blockIdx.x * 128;

    // norms -> smem (1024 floats)
    ((float4*)nsm)[tid] = ((const float4*)g_nrm)[tid];

    // start B tile 0 copy
    copy_tile(0, smem, tid);
    CP_COMMIT();

    // A fragments: 16 positions (warp), 64 dims, hi+lo  -> 64 regs
    uint32_t Ah[8][4], Al[8][4];
    {
        const int pr = p0 + warp * 16 + r;
        const float* zh = g_zh + (size_t)pr * C_DIM;
        const float* zl = g_zl + (size_t)pr * C_DIM;
        const int sw = ((r & 3) << 2) | ((r >> 2) & 1);
#pragma unroll
        for (int ks = 0; ks < 8; ks++) {
            int q = (((ks * 4 + c0) ^ sw)) * 2;
            float2 h0 = *(const float2*)(zh + q);
            float2 h8 = *(const float2*)(zh + 8 * C_DIM + q);
            Ah[ks][0] = __float_as_uint(h0.x); Ah[ks][2] = __float_as_uint(h0.y);
            Ah[ks][1] = __float_as_uint(h8.x); Ah[ks][3] = __float_as_uint(h8.y);
            float2 l0 = *(const float2*)(zl + q);
            float2 l8 = *(const float2*)(zl + 8 * C_DIM + q);
            Al[ks][0] = __float_as_uint(l0.x); Al[ks][2] = __float_as_uint(l0.y);
            Al[ks][1] = __float_as_uint(l8.x); Al[ks][3] = __float_as_uint(l8.y);
        }
    }

    float bestA = 3.402823466e+38f, bestB = 3.402823466e+38f;
    int   kA = 0, kB = 0;

    for (int t = 0; t < NBT; t++) {
        __syncthreads();                           // prev compute done with buf (t+1)&1
        if (t + 1 < NBT) {
            copy_tile(t + 1, smem + (size_t)((t + 1) & 1) * 65536, tid);
            CP_COMMIT();
            CP_WAIT1();                            // tile t landed
        } else {
            CP_WAIT0();
        }
        __syncthreads();

        const char* buf = smem + (size_t)(t & 1) * 65536;
        const int sw = ((r & 3) << 2) | ((r >> 2) & 1);

        for (int nt2 = 0; nt2 < 8; nt2++) {
            const int  lrow = nt2 * 16;
            const int  n0   = t * BTILE + lrow;    // global code base; pair covers n0..n0+15
            const char* bh  = buf + (size_t)(lrow + r) * 256;
            const char* bl  = bh + 32768;

            float2 nv0 = *(const float2*)(nsm + n0 + 2 * c0);
            float2 nv1 = *(const float2*)(nsm + n0 + 8 + 2 * c0);
            float hh0[4] = { nv0.x, nv0.y, nv0.x, nv0.y };
            float hh1[4] = { nv1.x, nv1.y, nv1.x, nv1.y };
            float hl0[4] = {0,0,0,0}, lh0[4] = {0,0,0,0};
            float hl1[4] = {0,0,0,0}, lh1[4] = {0,0,0,0};

#pragma unroll
            for (int ks = 0; ks < 8; ks++) {
                int off = ((ks * 4 + c0) ^ sw) * 8;
                uint2 b0h = *(const uint2*)(bh + off);
                uint2 b0l = *(const uint2*)(bl + off);
                uint2 b1h = *(const uint2*)(bh + 8 * 256 + off);
                uint2 b1l = *(const uint2*)(bl + 8 * 256 + off);
                mma8(hh0, Ah[ks], b0h); mma8(hl0, Ah[ks], b0l); mma8(lh0, Al[ks], b0h);
                mma8(hh1, Ah[ks], b1h); mma8(hl1, Ah[ks], b1l); mma8(lh1, Al[ks], b1h);
            }

            // epilogue: dist = norm + hh + hl + lh; running argmin (ascending k, strict <)
            {
                int e = n0 + 2 * c0;
                float d0 = (hh0[0] + hl0[0]) + lh0[0];
                float d1 = (hh0[1] + hl0[1]) + lh0[1];
                float d2 = (hh0[2] + hl0[2]) + lh0[2];
                float d3 = (hh0[3] + hl0[3]) + lh0[3];
                if (d0 < bestA) { bestA = d0; kA = e; }
                if (d1 < bestA) { bestA = d1; kA = e + 1; }
                if (d2 < bestB) { bestB = d2; kB = e; }
                if (d3 < bestB) { bestB = d3; kB = e + 1; }
            }
            {
                int e = n0 + 8 + 2 * c0;
                float d0 = (hh1[0] + hl1[0]) + lh1[0];
                float d1 = (hh1[1] + hl1[1]) + lh1[1];
                float d2 = (hh1[2] + hl1[2]) + lh1[2];
                float d3 = (hh1[3] + hl1[3]) + lh1[3];
                if (d0 < bestA) { bestA = d0; kA = e; }
                if (d1 < bestA) { bestA = d1; kA = e + 1; }
                if (d2 < bestB) { bestB = d2; kB = e; }
                if (d3 < bestB) { bestB = d3; kB = e + 1; }
            }
        }
    }

    // reduce across the 4 lanes (c0) sharing each row; index tie-break -> smallest k
#pragma unroll
    for (int off = 1; off <= 2; off <<= 1) {
        float vb = __shfl_xor_sync(0xFFFFFFFFu, bestA, off);
        int   vk = __shfl_xor_sync(0xFFFFFFFFu, kA, off);
        if (vb < bestA || (vb == bestA && vk < kA)) { bestA = vb; kA = vk; }
        vb = __shfl_xor_sync(0xFFFFFFFFu, bestB, off);
        vk = __shfl_xor_sync(0xFFFFFFFFu, kB, off);
        if (vb < bestB || (vb == bestB && vk < kB)) { bestB = vb; kB = vk; }
    }
    if (c0 == 0) {
        sIdx[warp * 16 + r]     = kA;
        sIdx[warp * 16 + r + 8] = kB;
    }
    __syncthreads();

    // gather winning codes (original fp32 emb) and scatter to [B,C,H,W]
    {
        const int pl = tid & 127;
        const int cb = (tid >> 7) * 32;
        const int k  = sIdx[pl];
        const float4* ev = (const float4*)(emb + (size_t)k * C_DIM + cb);
        const int b = p0 >> 12, hw0 = p0 & (HW - 1);
        float* op = out + (size_t)b * C_DIM * HW + hw0 + pl;
#pragma unroll
        for (int c4 = 0; c4 < 8; c4++) {
            float4 v = ev[c4];
            op[(size_t)(cb + c4 * 4 + 0) * HW] = v.x;
            op[(size_t)(cb + c4 * 4 + 1) * HW] = v.y;
            op[(size_t)(cb + c4 * 4 + 2) * HW] = v.z;
            op[(size_t)(cb + c4 * 4 + 3) * HW] = v.w;
        }
    }
}

// ---------- launch ----------
extern "C" void kernel_launch(void* const* d_in, const int* in_sizes, int n_in,
                              void* d_out, int out_size)
{
    const float* z_e = (const float*)d_in[0];   // [32, 64, 64, 64]
    const float* emb = (const float*)d_in[1];   // [1024, 64]
    float*       out = (float*)d_out;

    cudaFuncSetAttribute(vq_mma, cudaFuncAttributeMaxDynamicSharedMemorySize, SM_TOT);

    prep_nrm<<<K_DIM / 256, 256>>>(emb);
    prep_e<<<K_DIM * C_DIM / 256, 256>>>(emb);
    prep_z<<<32 * 64, 256>>>(z_e);
    vq_mma<<<NPOS / 128, 256, SM_TOT>>>(emb, out);
}

// round 6
// speedup vs baseline: 2.3736x; 1.0920x over previous
#include <cuda_runtime.h>
#include <cstdint>

#define C_DIM  64
#define K_DIM  1024
#define HW     4096
#define NPOS   131072
#define MTILE  64                  // positions per CTA
#define BTILE  64                  // codes per smem tile
#define NBT    (K_DIM / BTILE)     // 16
#define NTHREADS 128

// ---------- static device scratch ----------
__device__ float g_zh[(size_t)NPOS * C_DIM];   // tf32 hi of -2*z, permuted rows
__device__ float g_zl[(size_t)NPOS * C_DIM];   // tf32 lo
__device__ float g_eh[K_DIM * C_DIM];          // tf32 hi of e, permuted rows
__device__ float g_el[K_DIM * C_DIM];          // tf32 lo
__device__ float g_nrm[K_DIM];                 // ||e_k||^2 (fp32 exact)

__device__ __forceinline__ float tf32_rna(float v) {
    uint32_t u; asm("cvt.rna.tf32.f32 %0, %1;" : "=r"(u) : "f"(v));
    return __uint_as_float(u);
}

// Fragment-order permutation of a 64-float row, swizzled by row low bits.
__device__ __forceinline__ int permq(int c, int r) {
    int u = ((c >> 3) * 4 + (c & 3)) ^ (((r & 3) << 2) | ((r >> 2) & 1));
    return u * 2 + ((c >> 2) & 1);
}

// ---------- prep kernels ----------
__global__ void prep_nrm(const float* __restrict__ emb) {
    int k = blockIdx.x * blockDim.x + threadIdx.x;
    const float4* e = (const float4*)(emb + (size_t)k * C_DIM);
    float s = 0.f;
#pragma unroll
    for (int i = 0; i < C_DIM / 4; i++) {
        float4 v = e[i];
        s += v.x * v.x + v.y * v.y + v.z * v.z + v.w * v.w;
    }
    g_nrm[k] = s;
}

__global__ void prep_e(const float* __restrict__ emb) {
    int i = blockIdx.x * 256 + threadIdx.x;        // 65536 elements
    int k = i >> 6, c = i & 63;
    float v  = emb[i];
    float hi = tf32_rna(v);
    float lo = tf32_rna(v - hi);
    int o = k * C_DIM + permq(c, k & 7);
    g_eh[o] = hi;
    g_el[o] = lo;
}

// [b][c][hw] -> permuted tf32 split of (-2z), row-major [p][64]
__global__ void prep_z(const float* __restrict__ z) {
    __shared__ float s[64][65];
    int b  = blockIdx.x >> 6;
    int x0 = (blockIdx.x & 63) * 64;
    const float* src = z + (size_t)b * C_DIM * HW + x0;
    int t = threadIdx.x;
#pragma unroll
    for (int i = 0; i < 16; i++) {
        int idx = t + i * 256;
        int c = idx >> 6, x = idx & 63;
        s[c][x] = -2.f * src[(size_t)c * HW + x];
    }
    __syncthreads();
    size_t prow = (size_t)b * HW + x0;
#pragma unroll
    for (int i = 0; i < 16; i++) {
        int idx = t + i * 256;
        int pl = idx >> 6, c = idx & 63;
        float v  = s[c][pl];
        float hi = tf32_rna(v);
        float lo = tf32_rna(v - hi);
        size_t o = (prow + pl) * C_DIM + permq(c, pl & 7);
        g_zh[o] = hi;
        g_zl[o] = lo;
    }
}

// ---------- mma + cp.async helpers ----------
__device__ __forceinline__ void mma8(float* d, const uint32_t* a, uint2 b) {
    asm volatile("mma.sync.aligned.m16n8k8.row.col.f32.tf32.tf32.f32 "
        "{%0,%1,%2,%3}, {%4,%5,%6,%7}, {%8,%9}, {%0,%1,%2,%3};"
        : "+f"(d[0]), "+f"(d[1]), "+f"(d[2]), "+f"(d[3])
        : "r"(a[0]), "r"(a[1]), "r"(a[2]), "r"(a[3]), "r"(b.x), "r"(b.y));
}
__device__ __forceinline__ void cp16(void* dst_smem, const void* src) {
    uint32_t d;
    asm("{ .reg .u64 t; cvta.to.shared.u64 t, %1; cvt.u32.u64 %0, t; }" : "=r"(d) : "l"(dst_smem));
    asm volatile("cp.async.cg.shared.global [%0], [%1], 16;" :: "r"(d), "l"(src) : "memory");
}
#define CP_COMMIT() asm volatile("cp.async.commit_group;" ::: "memory")
#define CP_WAIT1()  asm volatile("cp.async.wait_group 1;" ::: "memory")
#define CP_WAIT0()  asm volatile("cp.async.wait_group 0;" ::: "memory")

// smem: B double buffer [2][64 codes x 256B hi | lo at +16KB] (64KB), norms 4KB, idx
#define SM_NRM  65536
#define SM_IDX  69632
#define SM_TOT  69888

// One tile = 64 codes, hi(16KB) + lo(16KB) = 2048 16B-units; 128 threads x 16.
__device__ __forceinline__ void copy_tile(int t, char* dst, int tid) {
#pragma unroll
    for (int i = 0; i < 16; i++) {
        int u = tid + i * NTHREADS;                // 0..2047
        const float* src = (i < 8)
            ? (g_eh + (size_t)(t * BTILE + (u >> 4)) * C_DIM + (u & 15) * 4)
            : (g_el + (size_t)(t * BTILE + ((u - 1024) >> 4)) * C_DIM + (u & 15) * 4);
        cp16(dst + (size_t)u * 16, src);
    }
}

// ---------- main kernel ----------
__global__ __launch_bounds__(NTHREADS, 3)
void vq_mma(const float* __restrict__ emb, float* __restrict__ out)
{
    extern __shared__ char smem[];
    float* nsm  = (float*)(smem + SM_NRM);
    int*   sIdx = (int*)(smem + SM_IDX);

    const int tid  = threadIdx.x;
    const int lane = tid & 31, warp = tid >> 5;    // 4 warps
    const int c0   = lane & 3, r = lane >> 2;      // r: 0..7
    const int p0   = blockIdx.x * MTILE;

    // norms -> smem (1024 floats over 128 threads)
    ((float4*)nsm)[tid]            = ((const float4*)g_nrm)[tid];
    ((float4*)nsm)[tid + NTHREADS] = ((const float4*)g_nrm)[tid + NTHREADS];

    // start B tile 0 copy
    copy_tile(0, smem, tid);
    CP_COMMIT();

    // A fragments: 16 positions (warp), 64 dims, hi+lo -> 64 regs
    uint32_t Ah[8][4], Al[8][4];
    {
        const int pr = p0 + warp * 16 + r;
        const float* zh = g_zh + (size_t)pr * C_DIM;
        const float* zl = g_zl + (size_t)pr * C_DIM;
        const int sw = ((r & 3) << 2) | ((r >> 2) & 1);
#pragma unroll
        for (int ks = 0; ks < 8; ks++) {
            int q = (((ks * 4 + c0) ^ sw)) * 2;
            float2 h0 = *(const float2*)(zh + q);
            float2 h8 = *(const float2*)(zh + 8 * C_DIM + q);
            Ah[ks][0] = __float_as_uint(h0.x); Ah[ks][2] = __float_as_uint(h0.y);
            Ah[ks][1] = __float_as_uint(h8.x); Ah[ks][3] = __float_as_uint(h8.y);
            float2 l0 = *(const float2*)(zl + q);
            float2 l8 = *(const float2*)(zl + 8 * C_DIM + q);
            Al[ks][0] = __float_as_uint(l0.x); Al[ks][2] = __float_as_uint(l0.y);
            Al[ks][1] = __float_as_uint(l8.x); Al[ks][3] = __float_as_uint(l8.y);
        }
    }

    float bestA = 3.402823466e+38f, bestB = 3.402823466e+38f;
    int   kA = 0, kB = 0;

    for (int t = 0; t < NBT; t++) {
        __syncthreads();                           // prev compute done with buf (t+1)&1
        if (t + 1 < NBT) {
            copy_tile(t + 1, smem + (size_t)((t + 1) & 1) * 32768, tid);
            CP_COMMIT();
            CP_WAIT1();                            // tile t landed
        } else {
            CP_WAIT0();
        }
        __syncthreads();

        const char* buf = smem + (size_t)(t & 1) * 32768;
        const int sw = ((r & 3) << 2) | ((r >> 2) & 1);

        for (int nt2 = 0; nt2 < BTILE / 16; nt2++) {
            const int  lrow = nt2 * 16;
            const int  n0   = t * BTILE + lrow;    // global code base; pair covers n0..n0+15
            const char* bh  = buf + (size_t)(lrow + r) * 256;
            const char* bl  = bh + 16384;

            float2 nv0 = *(const float2*)(nsm + n0 + 2 * c0);
            float2 nv1 = *(const float2*)(nsm + n0 + 8 + 2 * c0);
            float hh0[4] = { nv0.x, nv0.y, nv0.x, nv0.y };
            float hh1[4] = { nv1.x, nv1.y, nv1.x, nv1.y };
            float hl0[4] = {0,0,0,0}, lh0[4] = {0,0,0,0};
            float hl1[4] = {0,0,0,0}, lh1[4] = {0,0,0,0};

#pragma unroll
            for (int ks = 0; ks < 8; ks++) {
                int off = ((ks * 4 + c0) ^ sw) * 8;
                uint2 b0h = *(const uint2*)(bh + off);
                uint2 b0l = *(const uint2*)(bl + off);
                uint2 b1h = *(const uint2*)(bh + 8 * 256 + off);
                uint2 b1l = *(const uint2*)(bl + 8 * 256 + off);
                mma8(hh0, Ah[ks], b0h); mma8(hl0, Ah[ks], b0l); mma8(lh0, Al[ks], b0h);
                mma8(hh1, Ah[ks], b1h); mma8(hl1, Ah[ks], b1l); mma8(lh1, Al[ks], b1h);
            }

            // epilogue: dist = norm + hh + hl + lh; running argmin (ascending k, strict <)
            {
                int e = n0 + 2 * c0;
                float d0 = (hh0[0] + hl0[0]) + lh0[0];
                float d1 = (hh0[1] + hl0[1]) + lh0[1];
                float d2 = (hh0[2] + hl0[2]) + lh0[2];
                float d3 = (hh0[3] + hl0[3]) + lh0[3];
                if (d0 < bestA) { bestA = d0; kA = e; }
                if (d1 < bestA) { bestA = d1; kA = e + 1; }
                if (d2 < bestB) { bestB = d2; kB = e; }
                if (d3 < bestB) { bestB = d3; kB = e + 1; }
            }
            {
                int e = n0 + 8 + 2 * c0;
                float d0 = (hh1[0] + hl1[0]) + lh1[0];
                float d1 = (hh1[1] + hl1[1]) + lh1[1];
                float d2 = (hh1[2] + hl1[2]) + lh1[2];
                float d3 = (hh1[3] + hl1[3]) + lh1[3];
                if (d0 < bestA) { bestA = d0; kA = e; }
                if (d1 < bestA) { bestA = d1; kA = e + 1; }
                if (d2 < bestB) { bestB = d2; kB = e; }
                if (d3 < bestB) { bestB = d3; kB = e + 1; }
            }
        }
    }

    // reduce across the 4 lanes (c0) sharing each row; tie-break -> smallest k
#pragma unroll
    for (int off = 1; off <= 2; off <<= 1) {
        float vb = __shfl_xor_sync(0xFFFFFFFFu, bestA, off);
        int   vk = __shfl_xor_sync(0xFFFFFFFFu, kA, off);
        if (vb < bestA || (vb == bestA && vk < kA)) { bestA = vb; kA = vk; }
        vb = __shfl_xor_sync(0xFFFFFFFFu, bestB, off);
        vk = __shfl_xor_sync(0xFFFFFFFFu, kB, off);
        if (vb < bestB || (vb == bestB && vk < kB)) { bestB = vb; kB = vk; }
    }
    if (c0 == 0) {
        sIdx[warp * 16 + r]     = kA;
        sIdx[warp * 16 + r + 8] = kB;
    }
    __syncthreads();

    // gather winning codes (original fp32 emb) and scatter to [B,C,H,W]
    {
        const int pl = tid & (MTILE - 1);
        const int cb = (tid >> 6) * 32;
        const int k  = sIdx[pl];
        const float4* ev = (const float4*)(emb + (size_t)k * C_DIM + cb);
        const int b = p0 >> 12, hw0 = p0 & (HW - 1);
        float* op = out + (size_t)b * C_DIM * HW + hw0 + pl;
#pragma unroll
        for (int c4 = 0; c4 < 8; c4++) {
            float4 v = ev[c4];
            op[(size_t)(cb + c4 * 4 + 0) * HW] = v.x;
            op[(size_t)(cb + c4 * 4 + 1) * HW] = v.y;
            op[(size_t)(cb + c4 * 4 + 2) * HW] = v.z;
            op[(size_t)(cb + c4 * 4 + 3) * HW] = v.w;
        }
    }
}

// ---------- launch ----------
extern "C" void kernel_launch(void* const* d_in, const int* in_sizes, int n_in,
                              void* d_out, int out_size)
{
    const float* z_e = (const float*)d_in[0];   // [32, 64, 64, 64]
    const float* emb = (const float*)d_in[1];   // [1024, 64]
    float*       out = (float*)d_out;

    cudaFuncSetAttribute(vq_mma, cudaFuncAttributeMaxDynamicSharedMemorySize, SM_TOT);

    prep_nrm<<<K_DIM / 256, 256>>>(emb);
    prep_e<<<K_DIM * C_DIM / 256, 256>>>(emb);
    prep_z<<<32 * 64, 256>>>(z_e);
    vq_mma<<<NPOS / MTILE, NTHREADS, SM_TOT>>>(emb, out);
}

// round 7
// speedup vs baseline: 4.0503x; 1.7064x over previous
#include <cuda_runtime.h>
#include <cuda_fp16.h>
#include <cstdint>

#define C_DIM  64
#define K_DIM  1024
#define HW     4096
#define NPOS   131072
#define MTILE  64                  // positions per CTA
#define BTILE  64                  // codes per smem tile
#define NBT    (K_DIM / BTILE)     // 16
#define NTHREADS 128
#define INV2048 4.8828125e-4f

// ---------- static device scratch ----------
// A fragments: [group(16pos)][hl][ks 0..3][lane 0..31] x 16B
__device__ uint4  g_zfrag[(size_t)(NPOS / 16) * 2 * 4 * 32];
__device__ __half g_eh[K_DIM * C_DIM];   // e hi, rows in permuted dim order
__device__ __half g_el[K_DIM * C_DIM];   // (e - hi) * 2048
__device__ float  g_nrm[K_DIM];

// permuted position of dim c within a row: chunk order per 16 dims:
// [0,1,8,9, 2,3,10,11, 4,5,12,13, 6,7,14,15]
__device__ __forceinline__ int permq16(int c) {
    int ks = c >> 4, w = c & 15;
    return 16 * ks + 4 * ((w >> 1) & 3) + (w & 1) + 2 * (w >> 3);
}

// ---------- prep kernels ----------
__global__ void prep_nrm(const float* __restrict__ emb) {
    int k = blockIdx.x * blockDim.x + threadIdx.x;
    const float4* e = (const float4*)(emb + (size_t)k * C_DIM);
    float s = 0.f;
#pragma unroll
    for (int i = 0; i < C_DIM / 4; i++) {
        float4 v = e[i];
        s += v.x * v.x + v.y * v.y + v.z * v.z + v.w * v.w;
    }
    g_nrm[k] = s;
}

__global__ void prep_e(const float* __restrict__ emb) {
    int i = blockIdx.x * 256 + threadIdx.x;        // 65536
    int k = i >> 6, c = i & 63;
    float v = emb[i];
    __half h = __float2half_rn(v);
    __half l = __float2half_rn((v - __half2float(h)) * 2048.f);
    int o = k * C_DIM + permq16(c);
    g_eh[o] = h;
    g_el[o] = l;
}

// [b][c][hw] -> per-lane packed fp16 A fragments of (-2z)
__global__ void prep_z(const float* __restrict__ z) {
    __shared__ float s[64][65];
    int b  = blockIdx.x >> 6;
    int x0 = (blockIdx.x & 63) * 64;
    const float* src = z + (size_t)b * C_DIM * HW + x0;
    int t = threadIdx.x;
#pragma unroll
    for (int i = 0; i < 16; i++) {
        int idx = t + i * 256;
        int c = idx >> 6, x = idx & 63;
        s[c][x] = -2.f * src[(size_t)c * HW + x];
    }
    __syncthreads();
    // 1024 chunks per 64-pos block; 256 threads x 4
    int g0 = (b * HW + x0) >> 4;                   // first group id of this block
#pragma unroll
    for (int i = 0; i < 4; i++) {
        int cid  = t + i * 256;
        int lane = cid & 31;
        int ks   = (cid >> 5) & 3;
        int hl   = (cid >> 7) & 1;
        int gl   = cid >> 8;                       // 0..3
        int r    = lane >> 2, c0 = lane & 3;
        int k0   = 16 * ks + 2 * c0;
        int pa   = gl * 16 + r;                    // local position row
        int pb   = pa + 8;
        float v[8] = { s[k0][pa],     s[k0 + 1][pa],
                       s[k0 + 8][pa], s[k0 + 9][pa],
                       s[k0][pb],     s[k0 + 1][pb],
                       s[k0 + 8][pb], s[k0 + 9][pb] };
        __half hv[8];
#pragma unroll
        for (int j = 0; j < 8; j++) {
            __half h = __float2half_rn(v[j]);
            hv[j] = hl ? __float2half_rn((v[j] - __half2float(h)) * 2048.f) : h;
        }
        uint4 o;
        o.x = ((uint32_t)__half_as_ushort(hv[1]) << 16) | __half_as_ushort(hv[0]);  // a0
        o.y = ((uint32_t)__half_as_ushort(hv[3]) << 16) | __half_as_ushort(hv[2]);  // a2
        o.z = ((uint32_t)__half_as_ushort(hv[5]) << 16) | __half_as_ushort(hv[4]);  // a1
        o.w = ((uint32_t)__half_as_ushort(hv[7]) << 16) | __half_as_ushort(hv[6]);  // a3
        g_zfrag[(size_t)(((g0 + gl) * 2 + hl) * 4 + ks) * 32 + lane] = o;
    }
}

// ---------- mma + cp.async ----------
__device__ __forceinline__ void mma16(float* d, uint4 a, uint2 b) {
    asm volatile("mma.sync.aligned.m16n8k16.row.col.f32.f16.f16.f32 "
        "{%0,%1,%2,%3}, {%4,%5,%6,%7}, {%8,%9}, {%0,%1,%2,%3};"
        : "+f"(d[0]), "+f"(d[1]), "+f"(d[2]), "+f"(d[3])
        : "r"(a.x), "r"(a.z), "r"(a.y), "r"(a.w), "r"(b.x), "r"(b.y));
}
__device__ __forceinline__ void cp16cp(void* dst_smem, const void* src) {
    uint32_t d;
    asm("{ .reg .u64 t; cvta.to.shared.u64 t, %1; cvt.u32.u64 %0, t; }" : "=r"(d) : "l"(dst_smem));
    asm volatile("cp.async.cg.shared.global [%0], [%1], 16;" :: "r"(d), "l"(src) : "memory");
}
#define CP_COMMIT() asm volatile("cp.async.commit_group;" ::: "memory")
#define CP_WAIT1()  asm volatile("cp.async.wait_group 1;" ::: "memory")
#define CP_WAIT0()  asm volatile("cp.async.wait_group 0;" ::: "memory")

// smem: B double buffer [2][hi 8KB | lo 8KB] = 32KB, norms 4KB, idx 256B
#define SM_NRM  32768
#define SM_IDX  36864
#define SM_TOT  37120

// tile = 64 codes x 128B x {hi,lo} = 1024 16B-chunks; swizzle by code-row low bits
__device__ __forceinline__ void copy_tile(int t, char* dst, int tid) {
#pragma unroll
    for (int i = 0; i < 8; i++) {
        int cid = tid + i * NTHREADS;              // 0..1023
        int j   = cid & 7;                         // 16B chunk in row
        int ra  = cid >> 3;                        // 0..127
        int hl  = ra >> 6, n = ra & 63;
        const char* src = (const char*)(hl ? g_el : g_eh)
                        + ((size_t)(t * BTILE + n) * C_DIM + j * 8) * 2;
        char* d = dst + hl * 8192 + n * 128 + (((2 * j) ^ ((n & 3) << 2)) * 8);
        cp16cp(d, src);
    }
}

// ---------- main kernel ----------
__global__ __launch_bounds__(NTHREADS, 4)
void vq_mma(const float* __restrict__ emb, float* __restrict__ out)
{
    extern __shared__ char smem[];
    float* nsm  = (float*)(smem + SM_NRM);
    int*   sIdx = (int*)(smem + SM_IDX);

    const int tid  = threadIdx.x;
    const int lane = tid & 31, warp = tid >> 5;
    const int c0   = lane & 3, r = lane >> 2;
    const int p0   = blockIdx.x * MTILE;

    // norms -> smem
    ((float4*)nsm)[tid]            = ((const float4*)g_nrm)[tid];
    ((float4*)nsm)[tid + NTHREADS] = ((const float4*)g_nrm)[tid + NTHREADS];

    copy_tile(0, smem, tid);
    CP_COMMIT();

    // A fragments: group = 16 positions per warp, 4 ks chunks, hi+lo = 8 uint4
    uint4 Ah[4], Al[4];
    {
        const int g = blockIdx.x * 4 + warp;
        const uint4* base = g_zfrag + (size_t)g * 2 * 4 * 32;
#pragma unroll
        for (int ks = 0; ks < 4; ks++) {
            Ah[ks] = base[(0 * 4 + ks) * 32 + lane];
            Al[ks] = base[(1 * 4 + ks) * 32 + lane];
        }
    }

    // B read offsets: byte = 32*(ks ^ (r&3)) + 8*c0  (row-XOR swizzle resolved)
    int koff[4];
#pragma unroll
    for (int ks = 0; ks < 4; ks++) koff[ks] = 32 * (ks ^ (r & 3)) + 8 * c0;

    float bestA = 3.402823466e+38f, bestB = 3.402823466e+38f;
    int   kA = 0, kB = 0;

    for (int t = 0; t < NBT; t++) {
        __syncthreads();
        if (t + 1 < NBT) {
            copy_tile(t + 1, smem + (size_t)((t + 1) & 1) * 16384, tid);
            CP_COMMIT();
            CP_WAIT1();
        } else {
            CP_WAIT0();
        }
        __syncthreads();

        const char* buf = smem + (size_t)(t & 1) * 16384;

        for (int nt2 = 0; nt2 < BTILE / 16; nt2++) {
            const int  lrow = nt2 * 16;
            const int  n0   = t * BTILE + lrow;
            const char* bA  = buf + (size_t)(lrow + r) * 128;

            float2 nv0 = *(const float2*)(nsm + n0 + 2 * c0);
            float2 nv1 = *(const float2*)(nsm + n0 + 8 + 2 * c0);
            float hh0[4] = { nv0.x, nv0.y, nv0.x, nv0.y };
            float hh1[4] = { nv1.x, nv1.y, nv1.x, nv1.y };
            float hl0[4] = {0,0,0,0}, lh0[4] = {0,0,0,0};
            float hl1[4] = {0,0,0,0}, lh1[4] = {0,0,0,0};

#pragma unroll
            for (int ks = 0; ks < 4; ks++) {
                uint2 b0h = *(const uint2*)(bA + koff[ks]);
                uint2 b0l = *(const uint2*)(bA + koff[ks] + 8192);
                uint2 b1h = *(const uint2*)(bA + koff[ks] + 1024);
                uint2 b1l = *(const uint2*)(bA + koff[ks] + 9216);
                mma16(hh0, Ah[ks], b0h); mma16(hl0, Ah[ks], b0l); mma16(lh0, Al[ks], b0h);
                mma16(hh1, Ah[ks], b1h); mma16(hl1, Ah[ks], b1l); mma16(lh1, Al[ks], b1h);
            }

            // dist = norm + hh + (hl + lh) * 2^-11 ; running argmin (ascending k, strict <)
            {
                int e = n0 + 2 * c0;
                float d0 = fmaf(hl0[0] + lh0[0], INV2048, hh0[0]);
                float d1 = fmaf(hl0[1] + lh0[1], INV2048, hh0[1]);
                float d2 = fmaf(hl0[2] + lh0[2], INV2048, hh0[2]);
                float d3 = fmaf(hl0[3] + lh0[3], INV2048, hh0[3]);
                if (d0 < bestA) { bestA = d0; kA = e; }
                if (d1 < bestA) { bestA = d1; kA = e + 1; }
                if (d2 < bestB) { bestB = d2; kB = e; }
                if (d3 < bestB) { bestB = d3; kB = e + 1; }
            }
            {
                int e = n0 + 8 + 2 * c0;
                float d0 = fmaf(hl1[0] + lh1[0], INV2048, hh1[0]);
                float d1 = fmaf(hl1[1] + lh1[1], INV2048, hh1[1]);
                float d2 = fmaf(hl1[2] + lh1[2], INV2048, hh1[2]);
                float d3 = fmaf(hl1[3] + lh1[3], INV2048, hh1[3]);
                if (d0 < bestA) { bestA = d0; kA = e; }
                if (d1 < bestA) { bestA = d1; kA = e + 1; }
                if (d2 < bestB) { bestB = d2; kB = e; }
                if (d3 < bestB) { bestB = d3; kB = e + 1; }
            }
        }
    }

    // reduce across the 4 c0 lanes sharing each position row; tie-break smallest k
#pragma unroll
    for (int off = 1; off <= 2; off <<= 1) {
        float vb = __shfl_xor_sync(0xFFFFFFFFu, bestA, off);
        int   vk = __shfl_xor_sync(0xFFFFFFFFu, kA, off);
        if (vb < bestA || (vb == bestA && vk < kA)) { bestA = vb; kA = vk; }
        vb = __shfl_xor_sync(0xFFFFFFFFu, bestB, off);
        vk = __shfl_xor_sync(0xFFFFFFFFu, kB, off);
        if (vb < bestB || (vb == bestB && vk < kB)) { bestB = vb; kB = vk; }
    }
    if (c0 == 0) {
        sIdx[warp * 16 + r]     = kA;
        sIdx[warp * 16 + r + 8] = kB;
    }
    __syncthreads();

    // gather winning codes (original fp32 emb) and scatter to [B,C,H,W]
    {
        const int pl = tid & (MTILE - 1);
        const int cb = (tid >> 6) * 32;
        const int k  = sIdx[pl];
        const float4* ev = (const float4*)(emb + (size_t)k * C_DIM + cb);
        const int b = p0 >> 12, hw0 = p0 & (HW - 1);
        float* op = out + (size_t)b * C_DIM * HW + hw0 + pl;
#pragma unroll
        for (int c4 = 0; c4 < 8; c4++) {
            float4 v = ev[c4];
            op[(size_t)(cb + c4 * 4 + 0) * HW] = v.x;
            op[(size_t)(cb + c4 * 4 + 1) * HW] = v.y;
            op[(size_t)(cb + c4 * 4 + 2) * HW] = v.z;
            op[(size_t)(cb + c4 * 4 + 3) * HW] = v.w;
        }
    }
}

// ---------- launch ----------
extern "C" void kernel_launch(void* const* d_in, const int* in_sizes, int n_in,
                              void* d_out, int out_size)
{
    const float* z_e = (const float*)d_in[0];   // [32, 64, 64, 64]
    const float* emb = (const float*)d_in[1];   // [1024, 64]
    float*       out = (float*)d_out;

    cudaFuncSetAttribute(vq_mma, cudaFuncAttributeMaxDynamicSharedMemorySize, SM_TOT);

    prep_nrm<<<K_DIM / 256, 256>>>(emb);
    prep_e<<<K_DIM * C_DIM / 256, 256>>>(emb);
    prep_z<<<32 * 64, 256>>>(z_e);
    vq_mma<<<NPOS / MTILE, NTHREADS, SM_TOT>>>(emb, out);
}

// round 9
// speedup vs baseline: 4.4334x; 1.0946x over previous
#include <cuda_runtime.h>
#include <cuda_fp16.h>
#include <cstdint>

#define C_DIM  64
#define K_DIM  1024
#define HW     4096
#define NPOS   131072
#define MTILE  64                  // positions per CTA
#define BTILE  64                  // codes per smem tile
#define NBT    (K_DIM / BTILE)     // 16
#define NTHREADS 128
#define INV2048 4.8828125e-4f

// ---------- static device scratch ----------
__device__ __half g_eh[K_DIM * C_DIM];   // e hi, rows in permuted dim order
__device__ __half g_el[K_DIM * C_DIM];   // (e - hi) * 2048
__device__ float  g_nrm[K_DIM];

// permuted position of dim c within a row: chunk order per 16 dims:
// [0,1,8,9, 2,3,10,11, 4,5,12,13, 6,7,14,15]
__device__ __forceinline__ int permq16(int c) {
    int ks = c >> 4, w = c & 15;
    return 16 * ks + 4 * ((w >> 1) & 3) + (w & 1) + 2 * (w >> 3);
}

// ---------- prep kernels ----------
__global__ void prep_nrm(const float* __restrict__ emb) {
    int k = blockIdx.x * blockDim.x + threadIdx.x;
    const float4* e = (const float4*)(emb + (size_t)k * C_DIM);
    float s = 0.f;
#pragma unroll
    for (int i = 0; i < C_DIM / 4; i++) {
        float4 v = e[i];
        s += v.x * v.x + v.y * v.y + v.z * v.z + v.w * v.w;
    }
    g_nrm[k] = s;
}

__global__ void prep_e(const float* __restrict__ emb) {
    int i = blockIdx.x * 256 + threadIdx.x;        // 65536
    int k = i >> 6, c = i & 63;
    float v = emb[i];
    __half h = __float2half_rn(v);
    __half l = __float2half_rn((v - __half2float(h)) * 2048.f);
    int o = k * C_DIM + permq16(c);
    g_eh[o] = h;
    g_el[o] = l;
}

// ---------- mma + cp.async ----------
__device__ __forceinline__ void mma16(float* d, uint4 a, uint2 b) {
    asm volatile("mma.sync.aligned.m16n8k16.row.col.f32.f16.f16.f32 "
        "{%0,%1,%2,%3}, {%4,%5,%6,%7}, {%8,%9}, {%0,%1,%2,%3};"
        : "+f"(d[0]), "+f"(d[1]), "+f"(d[2]), "+f"(d[3])
        : "r"(a.x), "r"(a.z), "r"(a.y), "r"(a.w), "r"(b.x), "r"(b.y));
}
__device__ __forceinline__ void cp16cp(void* dst_smem, const void* src) {
    uint32_t d;
    asm("{ .reg .u64 t; cvta.to.shared.u64 t, %1; cvt.u32.u64 %0, t; }" : "=r"(d) : "l"(dst_smem));
    asm volatile("cp.async.cg.shared.global [%0], [%1], 16;" :: "r"(d), "l"(src) : "memory");
}
#define CP_COMMIT() asm volatile("cp.async.commit_group;" ::: "memory")
#define CP_WAIT1()  asm volatile("cp.async.wait_group 1;" ::: "memory")
#define CP_WAIT0()  asm volatile("cp.async.wait_group 0;" ::: "memory")

// smem: B double buffer [2][hi 8KB | lo 8KB] = 32KB, norms 4KB, idx 256B
// z-transpose scratch (16KB, stride 64) overlays buf1 [16384..32768) during startup.
#define SM_NRM  32768
#define SM_IDX  36864
#define SM_TOT  37120

// tile = 64 codes x 128B x {hi,lo} = 1024 16B-chunks; swizzle by code-row low bits
__device__ __forceinline__ void copy_tile(int t, char* dst, int tid) {
#pragma unroll
    for (int i = 0; i < 8; i++) {
        int cid = tid + i * NTHREADS;              // 0..1023
        int j   = cid & 7;                         // 16B chunk in row
        int ra  = cid >> 3;                        // 0..127
        int hl  = ra >> 6, n = ra & 63;
        const char* src = (const char*)(hl ? g_el : g_eh)
                        + ((size_t)(t * BTILE + n) * C_DIM + j * 8) * 2;
        char* d = dst + hl * 8192 + n * 128 + (((2 * j) ^ ((n & 3) << 2)) * 8);
        cp16cp(d, src);
    }
}

__device__ __forceinline__ uint32_t packh2(float a, float b) {
    __half2 h = __floats2half2_rn(a, b);
    return *(uint32_t*)&h;
}

// ---------- main kernel ----------
__global__ __launch_bounds__(NTHREADS, 4)
void vq_mma(const float* __restrict__ z_e, const float* __restrict__ emb,
            float* __restrict__ out)
{
    extern __shared__ char smem[];
    float* nsm  = (float*)(smem + SM_NRM);
    int*   sIdx = (int*)(smem + SM_IDX);
    float* ztr  = (float*)(smem + 16384);          // [64 dims][64 pos], stride 64

    const int tid  = threadIdx.x;
    const int lane = tid & 31, warp = tid >> 5;
    const int c0   = lane & 3, r = lane >> 2;
    const int p0   = blockIdx.x * MTILE;
    const int b    = p0 >> 12, hw0 = p0 & (HW - 1);

    // norms -> smem
    ((float4*)nsm)[tid]            = ((const float4*)g_nrm)[tid];
    ((float4*)nsm)[tid + NTHREADS] = ((const float4*)g_nrm)[tid + NTHREADS];

    // ---- load this CTA's z slab: ztr[c][x] = -2 * z[b, c, hw0 + x] ----
    {
        const float* zsrc = z_e + (size_t)b * C_DIM * HW + hw0;
#pragma unroll
        for (int i = 0; i < 8; i++) {
            int idx = tid + i * NTHREADS;          // 0..1023 float4 units
            int c = idx >> 4, x4 = idx & 15;
            float4 v = *(const float4*)(zsrc + (size_t)c * HW + x4 * 4);
            v.x *= -2.f; v.y *= -2.f; v.z *= -2.f; v.w *= -2.f;
            *(float4*)(ztr + c * 64 + x4 * 4) = v;
        }
    }
    __syncthreads();

    // buf0 [0..16384) is untouched by ztr: start tile 0 copy now (overlaps frag build)
    copy_tile(0, smem, tid);
    CP_COMMIT();

    // ---- build A fragments in-register (exact prep_z lane mapping) ----
    uint4 Ah[4], Al[4];
    {
        const int pa = warp * 16 + r, pb = pa + 8;
#pragma unroll
        for (int ks = 0; ks < 4; ks++) {
            int k0 = 16 * ks + 2 * c0;
            float v0 = ztr[(k0    ) * 64 + pa], v1 = ztr[(k0 + 1) * 64 + pa];
            float v2 = ztr[(k0 + 8) * 64 + pa], v3 = ztr[(k0 + 9) * 64 + pa];
            float v4 = ztr[(k0    ) * 64 + pb], v5 = ztr[(k0 + 1) * 64 + pb];
            float v6 = ztr[(k0 + 8) * 64 + pb], v7 = ztr[(k0 + 9) * 64 + pb];
            float h0 = __half2float(__float2half_rn(v0));
            float h1 = __half2float(__float2half_rn(v1));
            float h2 = __half2float(__float2half_rn(v2));
            float h3 = __half2float(__float2half_rn(v3));
            float h4 = __half2float(__float2half_rn(v4));
            float h5 = __half2float(__float2half_rn(v5));
            float h6 = __half2float(__float2half_rn(v6));
            float h7 = __half2float(__float2half_rn(v7));
            Ah[ks].x = packh2(h0, h1); Ah[ks].y = packh2(h2, h3);
            Ah[ks].z = packh2(h4, h5); Ah[ks].w = packh2(h6, h7);
            Al[ks].x = packh2((v0 - h0) * 2048.f, (v1 - h1) * 2048.f);
            Al[ks].y = packh2((v2 - h2) * 2048.f, (v3 - h3) * 2048.f);
            Al[ks].z = packh2((v4 - h4) * 2048.f, (v5 - h5) * 2048.f);
            Al[ks].w = packh2((v6 - h6) * 2048.f, (v7 - h7) * 2048.f);
        }
    }

    // B read offsets: byte = 32*(ks ^ (r&3)) + 8*c0  (row-XOR swizzle resolved)
    int koff[4];
#pragma unroll
    for (int ks = 0; ks < 4; ks++) koff[ks] = 32 * (ks ^ (r & 3)) + 8 * c0;

    float bestA = 3.402823466e+38f, bestB = 3.402823466e+38f;
    int   kA = 0, kB = 0;

    for (int t = 0; t < NBT; t++) {
        __syncthreads();                           // also protects ztr before buf1 reuse
        if (t + 1 < NBT) {
            copy_tile(t + 1, smem + (size_t)((t + 1) & 1) * 16384, tid);
            CP_COMMIT();
            CP_WAIT1();
        } else {
            CP_WAIT0();
        }
        __syncthreads();

        const char* buf = smem + (size_t)(t & 1) * 16384;

        for (int nt2 = 0; nt2 < BTILE / 16; nt2++) {
            const int  lrow = nt2 * 16;
            const int  n0   = t * BTILE + lrow;
            const char* bA  = buf + (size_t)(lrow + r) * 128;

            float2 nv0 = *(const float2*)(nsm + n0 + 2 * c0);
            float2 nv1 = *(const float2*)(nsm + n0 + 8 + 2 * c0);
            float hh0[4] = { nv0.x, nv0.y, nv0.x, nv0.y };
            float hh1[4] = { nv1.x, nv1.y, nv1.x, nv1.y };
            float hl0[4] = {0,0,0,0}, lh0[4] = {0,0,0,0};
            float hl1[4] = {0,0,0,0}, lh1[4] = {0,0,0,0};

#pragma unroll
            for (int ks = 0; ks < 4; ks++) {
                uint2 b0h = *(const uint2*)(bA + koff[ks]);
                uint2 b0l = *(const uint2*)(bA + koff[ks] + 8192);
                uint2 b1h = *(const uint2*)(bA + koff[ks] + 1024);
                uint2 b1l = *(const uint2*)(bA + koff[ks] + 9216);
                mma16(hh0, Ah[ks], b0h); mma16(hl0, Ah[ks], b0l); mma16(lh0, Al[ks], b0h);
                mma16(hh1, Ah[ks], b1h); mma16(hl1, Ah[ks], b1l); mma16(lh1, Al[ks], b1h);
            }

            // dist = norm + hh + (hl + lh) * 2^-11 ; running argmin (ascending k, strict <)
            {
                int e = n0 + 2 * c0;
                float d0 = fmaf(hl0[0] + lh0[0], INV2048, hh0[0]);
                float d1 = fmaf(hl0[1] + lh0[1], INV2048, hh0[1]);
                float d2 = fmaf(hl0[2] + lh0[2], INV2048, hh0[2]);
                float d3 = fmaf(hl0[3] + lh0[3], INV2048, hh0[3]);
                if (d0 < bestA) { bestA = d0; kA = e; }
                if (d1 < bestA) { bestA = d1; kA = e + 1; }
                if (d2 < bestB) { bestB = d2; kB = e; }
                if (d3 < bestB) { bestB = d3; kB = e + 1; }
            }
            {
                int e = n0 + 8 + 2 * c0;
                float d0 = fmaf(hl1[0] + lh1[0], INV2048, hh1[0]);
                float d1 = fmaf(hl1[1] + lh1[1], INV2048, hh1[1]);
                float d2 = fmaf(hl1[2] + lh1[2], INV2048, hh1[2]);
                float d3 = fmaf(hl1[3] + lh1[3], INV2048, hh1[3]);
                if (d0 < bestA) { bestA = d0; kA = e; }
                if (d1 < bestA) { bestA = d1; kA = e + 1; }
                if (d2 < bestB) { bestB = d2; kB = e; }
                if (d3 < bestB) { bestB = d3; kB = e + 1; }
            }
        }
    }

    // reduce across the 4 c0 lanes sharing each position row; tie-break smallest k
#pragma unroll
    for (int off = 1; off <= 2; off <<= 1) {
        float vb = __shfl_xor_sync(0xFFFFFFFFu, bestA, off);
        int   vk = __shfl_xor_sync(0xFFFFFFFFu, kA, off);
        if (vb < bestA || (vb == bestA && vk < kA)) { bestA = vb; kA = vk; }
        vb = __shfl_xor_sync(0xFFFFFFFFu, bestB, off);
        vk = __shfl_xor_sync(0xFFFFFFFFu, kB, off);
        if (vb < bestB || (vb == bestB && vk < kB)) { bestB = vb; kB = vk; }
    }
    if (c0 == 0) {
        sIdx[warp * 16 + r]     = kA;
        sIdx[warp * 16 + r + 8] = kB;
    }
    __syncthreads();

    // gather winning codes (original fp32 emb) and scatter to [B,C,H,W]
    {
        const int pl = tid & (MTILE - 1);
        const int cb = (tid >> 6) * 32;
        const int k  = sIdx[pl];
        const float4* ev = (const float4*)(emb + (size_t)k * C_DIM + cb);
        float* op = out + (size_t)b * C_DIM * HW + hw0 + pl;
#pragma unroll
        for (int c4 = 0; c4 < 8; c4++) {
            float4 v = ev[c4];
            op[(size_t)(cb + c4 * 4 + 0) * HW] = v.x;
            op[(size_t)(cb + c4 * 4 + 1) * HW] = v.y;
            op[(size_t)(cb + c4 * 4 + 2) * HW] = v.z;
            op[(size_t)(cb + c4 * 4 + 3) * HW] = v.w;
        }
    }
}

// ---------- launch ----------
extern "C" void kernel_launch(void* const* d_in, const int* in_sizes, int n_in,
                              void* d_out, int out_size)
{
    const float* z_e = (const float*)d_in[0];   // [32, 64, 64, 64]
    const float* emb = (const float*)d_in[1];   // [1024, 64]
    float*       out = (float*)d_out;

    cudaFuncSetAttribute(vq_mma, cudaFuncAttributeMaxDynamicSharedMemorySize, SM_TOT);

    prep_nrm<<<K_DIM / 256, 256>>>(emb);
    prep_e<<<K_DIM * C_DIM / 256, 256>>>(emb);
    vq_mma<<<NPOS / MTILE, NTHREADS, SM_TOT>>>(z_e, emb, out);
}

// round 10
// speedup vs baseline: 4.8048x; 1.0838x over previous
#include <cuda_runtime.h>
#include <cuda_fp16.h>
#include <cstdint>

#define C_DIM  64
#define K_DIM  1024
#define HW     4096
#define NPOS   131072
#define MTILE  64                  // positions per CTA
#define BTILE  64                  // codes per smem tile
#define NBT    (K_DIM / BTILE)     // 16
#define NTHREADS 128
#define INV2048 4.8828125e-4f

// ---------- static device scratch ----------
// Pre-built smem tile images: [tile t][hi 8KB | lo 8KB].
// Within a tile: (nt2, r, kk, c0, slot) -> nt2*2048 + r*256 + kk*64 + c0*16 + slot*8
//   code n = t*64 + nt2*16 + slot*8 + r ; kk = ks ^ (r & 3)
//   8B unit (ks, c0) holds dims {16ks+2c0, +1, +8, +9} as 4 halves.
__device__ char  g_ebuf[NBT * 16384];
__device__ float g_nrm[K_DIM];

// ---------- fused prep: norms + fp16 hi/lo split + tile-image scatter ----------
__global__ void prep(const float* __restrict__ emb) {
    const int t = threadIdx.x;
    const int k = blockIdx.x * 64 + (t >> 2);    // code row
    const int q = t & 3;                         // ks block (16 dims)
    const float4* src = (const float4*)(emb + (size_t)k * C_DIM + q * 16);
    float4 v0 = src[0], v1 = src[1], v2 = src[2], v3 = src[3];
    float w[16] = { v0.x, v0.y, v0.z, v0.w, v1.x, v1.y, v1.z, v1.w,
                    v2.x, v2.y, v2.z, v2.w, v3.x, v3.y, v3.z, v3.w };

    // partial norm over this quarter, reduce across the 4 lanes of the quad
    float s = 0.f;
#pragma unroll
    for (int i = 0; i < 16; i++) s += w[i] * w[i];
    s += __shfl_xor_sync(0xFFFFFFFFu, s, 1);
    s += __shfl_xor_sync(0xFFFFFFFFu, s, 2);
    if (q == 0) g_nrm[k] = s;

    // destination base for this (k, ks=q)
    const int tt = k >> 6, n = k & 63;
    const int nt2 = n >> 4, rr = n & 15, slot = rr >> 3, r = rr & 7;
    char* base = g_ebuf + (size_t)tt * 16384 + nt2 * 2048 + r * 256
               + ((q ^ (r & 3)) * 64) + slot * 8;
#pragma unroll
    for (int c0 = 0; c0 < 4; c0++) {
        float a0 = w[2 * c0], a1 = w[2 * c0 + 1], a2 = w[2 * c0 + 8], a3 = w[2 * c0 + 9];
        __half h0 = __float2half_rn(a0), h1 = __float2half_rn(a1);
        __half h2 = __float2half_rn(a2), h3 = __float2half_rn(a3);
        __half hv[4] = { h0, h1, h2, h3 };
        __half lv[4] = { __float2half_rn((a0 - __half2float(h0)) * 2048.f),
                         __float2half_rn((a1 - __half2float(h1)) * 2048.f),
                         __float2half_rn((a2 - __half2float(h2)) * 2048.f),
                         __float2half_rn((a3 - __half2float(h3)) * 2048.f) };
        *(uint64_t*)(base + c0 * 16)        = *(uint64_t*)hv;
        *(uint64_t*)(base + c0 * 16 + 8192) = *(uint64_t*)lv;
    }
}

// ---------- mma + cp.async ----------
__device__ __forceinline__ void mma16(float* d, uint4 a, uint32_t bx, uint32_t by) {
    asm volatile("mma.sync.aligned.m16n8k16.row.col.f32.f16.f16.f32 "
        "{%0,%1,%2,%3}, {%4,%5,%6,%7}, {%8,%9}, {%0,%1,%2,%3};"
        : "+f"(d[0]), "+f"(d[1]), "+f"(d[2]), "+f"(d[3])
        : "r"(a.x), "r"(a.z), "r"(a.y), "r"(a.w), "r"(bx), "r"(by));
}
__device__ __forceinline__ void cp16cp(void* dst_smem, const void* src) {
    uint32_t d;
    asm("{ .reg .u64 t; cvta.to.shared.u64 t, %1; cvt.u32.u64 %0, t; }" : "=r"(d) : "l"(dst_smem));
    asm volatile("cp.async.cg.shared.global [%0], [%1], 16;" :: "r"(d), "l"(src) : "memory");
}
#define CP_COMMIT() asm volatile("cp.async.commit_group;" ::: "memory")
#define CP_WAIT1()  asm volatile("cp.async.wait_group 1;" ::: "memory")
#define CP_WAIT0()  asm volatile("cp.async.wait_group 0;" ::: "memory")

// smem: B double buffer 2 x 16KB, norms 4KB, idx 256B; ztr overlays buf1 at startup
#define SM_NRM  32768
#define SM_IDX  36864
#define SM_TOT  37120

// pure linear tile copy: 16KB, 128 threads x 8 x 16B
__device__ __forceinline__ void copy_tile(int t, char* dst, int tid) {
    const char* src = g_ebuf + (size_t)t * 16384;
#pragma unroll
    for (int i = 0; i < 8; i++) {
        int u = (tid + i * NTHREADS) * 16;
        cp16cp(dst + u, src + u);
    }
}

__device__ __forceinline__ uint32_t packh2(float a, float b) {
    __half2 h = __floats2half2_rn(a, b);
    return *(uint32_t*)&h;
}

// ---------- main kernel ----------
__global__ __launch_bounds__(NTHREADS, 4)
void vq_mma(const float* __restrict__ z_e, const float* __restrict__ emb,
            float* __restrict__ out)
{
    extern __shared__ char smem[];
    float* nsm  = (float*)(smem + SM_NRM);
    int*   sIdx = (int*)(smem + SM_IDX);
    float* ztr  = (float*)(smem + 16384);          // [64 dims][64 pos]

    const int tid  = threadIdx.x;
    const int lane = tid & 31, warp = tid >> 5;
    const int c0   = lane & 3, r = lane >> 2;
    const int p0   = blockIdx.x * MTILE;
    const int b    = p0 >> 12, hw0 = p0 & (HW - 1);

    // norms -> smem
    ((float4*)nsm)[tid]            = ((const float4*)g_nrm)[tid];
    ((float4*)nsm)[tid + NTHREADS] = ((const float4*)g_nrm)[tid + NTHREADS];

    // ---- load this CTA's z slab: ztr[c][x] = -2 * z[b, c, hw0 + x] ----
    {
        const float* zsrc = z_e + (size_t)b * C_DIM * HW + hw0;
#pragma unroll
        for (int i = 0; i < 8; i++) {
            int idx = tid + i * NTHREADS;          // 0..1023 float4 units
            int c = idx >> 4, x4 = idx & 15;
            float4 v = *(const float4*)(zsrc + (size_t)c * HW + x4 * 4);
            v.x *= -2.f; v.y *= -2.f; v.z *= -2.f; v.w *= -2.f;
            *(float4*)(ztr + c * 64 + x4 * 4) = v;
        }
    }
    __syncthreads();

    // buf0 untouched by ztr: start tile 0 copy now
    copy_tile(0, smem, tid);
    CP_COMMIT();

    // ---- build A fragments in-register ----
    uint4 Ah[4], Al[4];
    {
        const int pa = warp * 16 + r, pb = pa + 8;
#pragma unroll
        for (int ks = 0; ks < 4; ks++) {
            int k0 = 16 * ks + 2 * c0;
            float v0 = ztr[(k0    ) * 64 + pa], v1 = ztr[(k0 + 1) * 64 + pa];
            float v2 = ztr[(k0 + 8) * 64 + pa], v3 = ztr[(k0 + 9) * 64 + pa];
            float v4 = ztr[(k0    ) * 64 + pb], v5 = ztr[(k0 + 1) * 64 + pb];
            float v6 = ztr[(k0 + 8) * 64 + pb], v7 = ztr[(k0 + 9) * 64 + pb];
            float h0 = __half2float(__float2half_rn(v0));
            float h1 = __half2float(__float2half_rn(v1));
            float h2 = __half2float(__float2half_rn(v2));
            float h3 = __half2float(__float2half_rn(v3));
            float h4 = __half2float(__float2half_rn(v4));
            float h5 = __half2float(__float2half_rn(v5));
            float h6 = __half2float(__float2half_rn(v6));
            float h7 = __half2float(__float2half_rn(v7));
            Ah[ks].x = packh2(h0, h1); Ah[ks].y = packh2(h2, h3);
            Ah[ks].z = packh2(h4, h5); Ah[ks].w = packh2(h6, h7);
            Al[ks].x = packh2((v0 - h0) * 2048.f, (v1 - h1) * 2048.f);
            Al[ks].y = packh2((v2 - h2) * 2048.f, (v3 - h3) * 2048.f);
            Al[ks].z = packh2((v4 - h4) * 2048.f, (v5 - h5) * 2048.f);
            Al[ks].w = packh2((v6 - h6) * 2048.f, (v7 - h7) * 2048.f);
        }
    }

    // per-ks byte offsets within this thread's row: (ks ^ (r&3))*64 + c0*16
    int kk[4];
#pragma unroll
    for (int ks = 0; ks < 4; ks++) kk[ks] = ((ks ^ (r & 3)) * 64) + c0 * 16;

    float bestA = 3.402823466e+38f, bestB = 3.402823466e+38f;
    int   kA = 0, kB = 0;

    for (int t = 0; t < NBT; t++) {
        __syncthreads();
        if (t + 1 < NBT) {
            copy_tile(t + 1, smem + (size_t)((t + 1) & 1) * 16384, tid);
            CP_COMMIT();
            CP_WAIT1();
        } else {
            CP_WAIT0();
        }
        __syncthreads();

        const char* buf = smem + (size_t)(t & 1) * 16384;

#pragma unroll
        for (int nt2 = 0; nt2 < BTILE / 16; nt2++) {
            const int  n0 = t * BTILE + nt2 * 16;
            const char* bA = buf + nt2 * 2048 + r * 256;

            float2 nv0 = *(const float2*)(nsm + n0 + 2 * c0);
            float2 nv1 = *(const float2*)(nsm + n0 + 8 + 2 * c0);
            float hh0[4] = { nv0.x, nv0.y, nv0.x, nv0.y };
            float hh1[4] = { nv1.x, nv1.y, nv1.x, nv1.y };
            float x0[4] = {0,0,0,0}, x1[4] = {0,0,0,0};

#pragma unroll
            for (int ks = 0; ks < 4; ks++) {
                uint4 bh = *(const uint4*)(bA + kk[ks]);
                uint4 bl = *(const uint4*)(bA + kk[ks] + 8192);
                mma16(hh0, Ah[ks], bh.x, bh.y);
                mma16(hh1, Ah[ks], bh.z, bh.w);
                mma16(x0,  Ah[ks], bl.x, bl.y);
                mma16(x0,  Al[ks], bh.x, bh.y);
                mma16(x1,  Ah[ks], bl.z, bl.w);
                mma16(x1,  Al[ks], bh.z, bh.w);
            }

            // dist = norm + hh + x * 2^-11 ; running argmin (ascending k, strict <)
            {
                int e = n0 + 2 * c0;
                float d0 = fmaf(x0[0], INV2048, hh0[0]);
                float d1 = fmaf(x0[1], INV2048, hh0[1]);
                float d2 = fmaf(x0[2], INV2048, hh0[2]);
                float d3 = fmaf(x0[3], INV2048, hh0[3]);
                if (d0 < bestA) { bestA = d0; kA = e; }
                if (d1 < bestA) { bestA = d1; kA = e + 1; }
                if (d2 < bestB) { bestB = d2; kB = e; }
                if (d3 < bestB) { bestB = d3; kB = e + 1; }
            }
            {
                int e = n0 + 8 + 2 * c0;
                float d0 = fmaf(x1[0], INV2048, hh1[0]);
                float d1 = fmaf(x1[1], INV2048, hh1[1]);
                float d2 = fmaf(x1[2], INV2048, hh1[2]);
                float d3 = fmaf(x1[3], INV2048, hh1[3]);
                if (d0 < bestA) { bestA = d0; kA = e; }
                if (d1 < bestA) { bestA = d1; kA = e + 1; }
                if (d2 < bestB) { bestB = d2; kB = e; }
                if (d3 < bestB) { bestB = d3; kB = e + 1; }
            }
        }
    }

    // reduce across the 4 c0 lanes sharing each position row; tie-break smallest k
#pragma unroll
    for (int off = 1; off <= 2; off <<= 1) {
        float vb = __shfl_xor_sync(0xFFFFFFFFu, bestA, off);
        int   vk = __shfl_xor_sync(0xFFFFFFFFu, kA, off);
        if (vb < bestA || (vb == bestA && vk < kA)) { bestA = vb; kA = vk; }
        vb = __shfl_xor_sync(0xFFFFFFFFu, bestB, off);
        vk = __shfl_xor_sync(0xFFFFFFFFu, kB, off);
        if (vb < bestB || (vb == bestB && vk < kB)) { bestB = vb; kB = vk; }
    }
    if (c0 == 0) {
        sIdx[warp * 16 + r]     = kA;
        sIdx[warp * 16 + r + 8] = kB;
    }
    __syncthreads();

    // gather winning codes (original fp32 emb) and scatter to [B,C,H,W]
    {
        const int pl = tid & (MTILE - 1);
        const int cb = (tid >> 6) * 32;
        const int k  = sIdx[pl];
        const float4* ev = (const float4*)(emb + (size_t)k * C_DIM + cb);
        float* op = out + (size_t)b * C_DIM * HW + hw0 + pl;
#pragma unroll
        for (int c4 = 0; c4 < 8; c4++) {
            float4 v = ev[c4];
            op[(size_t)(cb + c4 * 4 + 0) * HW] = v.x;
            op[(size_t)(cb + c4 * 4 + 1) * HW] = v.y;
            op[(size_t)(cb + c4 * 4 + 2) * HW] = v.z;
            op[(size_t)(cb + c4 * 4 + 3) * HW] = v.w;
        }
    }
}

// ---------- launch ----------
extern "C" void kernel_launch(void* const* d_in, const int* in_sizes, int n_in,
                              void* d_out, int out_size)
{
    const float* z_e = (const float*)d_in[0];   // [32, 64, 64, 64]
    const float* emb = (const float*)d_in[1];   // [1024, 64]
    float*       out = (float*)d_out;

    cudaFuncSetAttribute(vq_mma, cudaFuncAttributeMaxDynamicSharedMemorySize, SM_TOT);

    prep<<<K_DIM / 64, 256>>>(emb);
    vq_mma<<<NPOS / MTILE, NTHREADS, SM_TOT>>>(z_e, emb, out);
}